// round 14
// baseline (speedup 1.0000x reference)
#include <cuda_runtime.h>
#include <cstddef>

// GloVe loss — exact two-level counting sort by center, with aux collapsed to
// TWO kernels using in-kernel grid barriers (all blocks co-resident by
// construction), plus the proven byte-bound main gather.
// Launches: K1 (hist+scan) -> K2 (scatter+sort) -> main.

static constexpr int EMB           = 300;
static constexpr int NV4           = EMB / 4;       // 75 float4 per row
static constexpr int BATCH_N       = 262144;

static constexpr int BUCKET_SHIFT  = 7;
static constexpr int NB            = 1024;          // covers 100000>>7 = 782
static constexpr int GRID2         = 782;           // K2 blocks == buckets

static constexpr int H1BLOCKS      = 128;
static constexpr int H1THREADS     = 512;
static constexpr int H1CHUNK       = BATCH_N / H1BLOCKS;   // 2048
static constexpr int H1SPT         = H1CHUNK / H1THREADS;  // 4

static constexpr int THREADS       = 256;
static constexpr int WARPS_PER_BLK = THREADS / 32;  // 8
static constexpr int ROWS_PER_WARP = 8;
static constexpr int MBLOCKS       = BATCH_N / (WARPS_PER_BLK * ROWS_PER_WARP); // 4096

// Replay-safe: g_cnt zeroed by K1 scan after read; g_base rewritten each
// launch; s_recs fully overwritten; g_bar0/g_bar1/g_acc/g_done reset by the
// last main block (main runs strictly after K1/K2 in stream order).
__device__ int          g_cnt[NB];
__device__ int          g_base[NB];
__device__ int4         s_recs[BATCH_N];
__device__ unsigned int g_bar0;
__device__ unsigned int g_bar1;
__device__ double       g_acc;
__device__ unsigned int g_done;

// ---- K1: histogram (all blocks) + scan (block 0 after grid barrier) ---------
__global__ __launch_bounds__(H1THREADS) void glove_k1_kernel(
    const int* __restrict__ center)
{
    __shared__ int h[NB];
    const int tid  = threadIdx.x;
    const int idx0 = blockIdx.x * H1CHUNK;

    for (int i = tid; i < NB; i += H1THREADS) h[i] = 0;
    __syncthreads();
    #pragma unroll
    for (int k = 0; k < H1SPT; ++k) {
        const int c = __ldg(center + idx0 + k * H1THREADS + tid);
        atomicAdd(&h[c >> BUCKET_SHIFT], 1);
    }
    __syncthreads();
    for (int b = tid; b < NB; b += H1THREADS)
        if (h[b]) atomicAdd(&g_cnt[b], h[b]);

    // Arrive on grid barrier; only block 0 continues (and waits for all).
    __syncthreads();
    if (tid == 0) {
        __threadfence();
        atomicAdd(&g_bar0, 1u);
        if (blockIdx.x == 0)
            while (atomicAdd(&g_bar0, 0u) < (unsigned)H1BLOCKS) __nanosleep(64);
    }
    if (blockIdx.x != 0) return;
    __syncthreads();
    __threadfence();

    // Scan phase (block 0, 512 threads, 2 counters each); re-zero counts.
    __shared__ int tmp[H1THREADS];
    const int v0 = g_cnt[2 * tid];
    const int v1 = g_cnt[2 * tid + 1];
    g_cnt[2 * tid]     = 0;
    g_cnt[2 * tid + 1] = 0;
    const int sv = v0 + v1;
    tmp[tid] = sv;
    __syncthreads();
    #pragma unroll
    for (int off = 1; off < H1THREADS; off <<= 1) {
        int u = (tid >= off) ? tmp[tid - off] : 0;
        __syncthreads();
        tmp[tid] += u;
        __syncthreads();
    }
    const int pref = tmp[tid] - sv;        // exclusive prefix
    g_base[2 * tid]     = pref;
    g_base[2 * tid + 1] = pref + v0;
}

// ---- K2: scatter (all 782 blocks) + grid barrier + in-bucket sort -----------
__global__ __launch_bounds__(THREADS, 6) void glove_k2_kernel(
    const int*   __restrict__ center,
    const int*   __restrict__ outside,
    const float* __restrict__ coocs,
    const float* __restrict__ weighting)
{
    __shared__ int h[NB];
    __shared__ int base[NB];
    const int b    = blockIdx.x;
    const int tid  = threadIdx.x;
    const int lane = tid & 31;
    const int warp = tid >> 5;

    // ---- scatter phase: this block handles input slice [i0, i1) ----
    const int i0 = (int)(((long long)b       * BATCH_N) / GRID2);
    const int i1 = (int)(((long long)(b + 1) * BATCH_N) / GRID2);
    const int m  = i1 - i0;                 // 335 or 336

    for (int i = tid; i < NB; i += THREADS) h[i] = 0;
    __syncthreads();

    int c0 = -1, c1 = -1;
    if (tid < m)            { c0 = __ldg(center + i0 + tid);           atomicAdd(&h[c0 >> BUCKET_SHIFT], 1); }
    if (tid + THREADS < m)  { c1 = __ldg(center + i0 + tid + THREADS); atomicAdd(&h[c1 >> BUCKET_SHIFT], 1); }
    __syncthreads();
    for (int bb = tid; bb < NB; bb += THREADS) {
        const int n = h[bb];
        base[bb] = n ? atomicAdd(&g_base[bb], n) : 0;
    }
    __syncthreads();
    for (int i = tid; i < NB; i += THREADS) h[i] = 0;   // reuse as cursors
    __syncthreads();

    if (c0 >= 0) {
        const int i = i0 + tid;
        int4 rec;
        rec.x = c0;
        rec.y = __ldg(outside + i);
        rec.z = __float_as_int(__ldg(coocs + i));
        rec.w = __float_as_int(__ldg(weighting + i));
        s_recs[base[c0 >> BUCKET_SHIFT] + atomicAdd(&h[c0 >> BUCKET_SHIFT], 1)] = rec;
    }
    if (c1 >= 0) {
        const int i = i0 + tid + THREADS;
        int4 rec;
        rec.x = c1;
        rec.y = __ldg(outside + i);
        rec.z = __float_as_int(__ldg(coocs + i));
        rec.w = __float_as_int(__ldg(weighting + i));
        s_recs[base[c1 >> BUCKET_SHIFT] + atomicAdd(&h[c1 >> BUCKET_SHIFT], 1)] = rec;
    }

    // ---- grid barrier: all scatters visible before any sort ----
    __syncthreads();
    if (tid == 0) {
        __threadfence();
        atomicAdd(&g_bar1, 1u);
        while (atomicAdd(&g_bar1, 0u) < (unsigned)GRID2) __nanosleep(64);
    }
    __syncthreads();
    __threadfence();

    // ---- sort phase: counting sort of bucket b by c&127 ----
    // Reuse h/base smem fronts as cnt/pos.
    int* cnt = h;
    int* pos = base;
    __shared__ int wsum[8];

    const int s = (b == 0) ? 0 : __ldg(&g_base[b - 1]);
    const int n = __ldg(&g_base[b]) - s;
    if (n <= 0 || n > 2 * THREADS) return;  // capacity guard (~never; perf-only)

    if (tid < 128) cnt[tid] = 0;
    __syncthreads();

    int4 r0, r1;
    const bool has0 = (tid < n);
    const bool has1 = (tid + THREADS < n);
    if (has0) { r0 = s_recs[s + tid];           atomicAdd(&cnt[r0.x & 127], 1); }
    if (has1) { r1 = s_recs[s + tid + THREADS]; atomicAdd(&cnt[r1.x & 127], 1); }
    __syncthreads();

    if (warp < 4) {                         // 4-warp shfl scan of 128 counters
        const int idx = warp * 32 + lane;
        const int x   = cnt[idx];
        int incl = x;
        #pragma unroll
        for (int off = 1; off < 32; off <<= 1) {
            int u = __shfl_up_sync(0xffffffffu, incl, off);
            if (lane >= off) incl += u;
        }
        if (lane == 31) wsum[warp] = incl;
        __syncwarp();
        pos[idx] = incl - x;
    }
    __syncthreads();
    if (tid < 128) {
        const int w = tid >> 5;
        int add = 0;
        #pragma unroll
        for (int k = 0; k < 3; ++k) if (k < w) add += wsum[k];
        pos[tid] += add;
    }
    __syncthreads();

    if (has0) s_recs[s + atomicAdd(&pos[r0.x & 127], 1)] = r0;
    if (has1) s_recs[s + atomicAdd(&pos[r1.x & 127], 1)] = r1;
}

// ---- main gather with center-row register reuse (R7/R12-proven) -------------
__global__ __launch_bounds__(THREADS, 6) void glove_main_kernel(
    const float* __restrict__ cemb,
    const float* __restrict__ oemb,
    const float* __restrict__ cbias,
    const float* __restrict__ obias,
    float*       __restrict__ out)
{
    const int lane  = threadIdx.x & 31;
    const int warp  = threadIdx.x >> 5;
    const int gwarp = blockIdx.x * WARPS_PER_BLK + warp;

    const float4* __restrict__ cemb4 = reinterpret_cast<const float4*>(cemb);
    const float4* __restrict__ oemb4 = reinterpret_cast<const float4*>(oemb);

    float wsum = 0.0f;
    int   prev = -1;
    float4 a0, a1, a2;
    float  cb = 0.0f;
    a0 = a1 = a2 = make_float4(0.f, 0.f, 0.f, 0.f);

    #pragma unroll 1
    for (int r = 0; r < ROWS_PER_WARP; ++r) {
        const int row = gwarp * ROWS_PER_WARP + r;
        const int4 rec = __ldg(&s_recs[row]);

        const unsigned oo = (unsigned)rec.y * (unsigned)NV4 + (unsigned)lane;
        float4 b0 = __ldg(oemb4 + oo);
        float4 b1 = __ldg(oemb4 + oo + 32);
        float4 b2 = make_float4(0.f, 0.f, 0.f, 0.f);
        if (lane < NV4 - 64) b2 = __ldg(oemb4 + oo + 64);
        const float obv = __ldg(obias + rec.y);

        if (rec.x != prev) {   // warp-uniform branch (records sorted by center)
            const unsigned co = (unsigned)rec.x * (unsigned)NV4 + (unsigned)lane;
            a0 = __ldg(cemb4 + co);
            a1 = __ldg(cemb4 + co + 32);
            a2 = make_float4(0.f, 0.f, 0.f, 0.f);
            if (lane < NV4 - 64) a2 = __ldg(cemb4 + co + 64);
            cb = __ldg(cbias + rec.x);
            prev = rec.x;
        }

        float dot = a0.x * b0.x + a0.y * b0.y + a0.z * b0.z + a0.w * b0.w;
        dot      += a1.x * b1.x + a1.y * b1.y + a1.z * b1.z + a1.w * b1.w;
        dot      += a2.x * b2.x + a2.y * b2.y + a2.z * b2.z + a2.w * b2.w;

        #pragma unroll
        for (int off = 16; off; off >>= 1)
            dot += __shfl_xor_sync(0xffffffffu, dot, off);

        if (lane == 0) {
            const float err = dot + cb + obv - __int_as_float(rec.z);
            wsum += __int_as_float(rec.w) * err * err;
        }
    }

    __shared__ float sh[WARPS_PER_BLK];
    if (lane == 0) sh[warp] = wsum;
    __syncthreads();

    if (threadIdx.x == 0) {
        float s = 0.0f;
        #pragma unroll
        for (int i = 0; i < WARPS_PER_BLK; ++i) s += sh[i];
        atomicAdd(&g_acc, (double)s);

        __threadfence();
        const unsigned t = atomicAdd(&g_done, 1u);
        if (t == (unsigned)(MBLOCKS - 1)) {
            const double v = atomicAdd(&g_acc, 0.0);
            out[0] = (float)v;
            g_acc  = 0.0;
            g_done = 0u;
            g_bar0 = 0u;    // reset K1/K2 barriers for next replay
            g_bar1 = 0u;
        }
    }
}

extern "C" void kernel_launch(void* const* d_in, const int* in_sizes, int n_in,
                              void* d_out, int out_size) {
    const int*   center    = (const int*)  d_in[0];
    const int*   outside   = (const int*)  d_in[1];
    const float* coocs     = (const float*)d_in[2];
    const float* weighting = (const float*)d_in[3];
    const float* cemb      = (const float*)d_in[4];
    const float* oemb      = (const float*)d_in[5];
    const float* cbias     = (const float*)d_in[6];
    const float* obias     = (const float*)d_in[7];
    float* out = (float*)d_out;

    glove_k1_kernel<<<H1BLOCKS, H1THREADS>>>(center);
    glove_k2_kernel<<<GRID2, THREADS>>>(center, outside, coocs, weighting);
    glove_main_kernel<<<MBLOCKS, THREADS>>>(cemb, oemb, cbias, obias, out);
}

// round 16
// speedup vs baseline: 1.0502x; 1.0502x over previous
#include <cuda_runtime.h>
#include <cstddef>

// GloVe loss — TWO launches.
//  aux  (grid 128 x 512, all blocks co-resident): hist -> grid barrier ->
//        block-0 scan (re-zeros counts) -> ready flag -> scatter (reuses
//        phase-1 smem hist; 128-block reserve keeps atomic chains short) ->
//        grid barrier -> each block counting-sorts ~6 buckets by c&127.
//  main (grid 4096 x 256): R7/R12-proven byte-bound gather with
//        register-held center-row reuse; resets all barriers/accumulators.

static constexpr int EMB           = 300;
static constexpr int NV4           = EMB / 4;       // 75 float4 per row
static constexpr int BATCH_N       = 262144;

static constexpr int BUCKET_SHIFT  = 7;
static constexpr int NB            = 1024;          // covers 100000>>7 = 782
static constexpr int NB_USED       = 782;

static constexpr int ABLOCKS       = 128;
static constexpr int ATHREADS      = 512;
static constexpr int ACHUNK        = BATCH_N / ABLOCKS;    // 2048
static constexpr int ASPT          = ACHUNK / ATHREADS;    // 4
static constexpr int SORT_CAP      = 1024;                 // bucket avg 335

static constexpr int THREADS       = 256;
static constexpr int WARPS_PER_BLK = THREADS / 32;  // 8
static constexpr int ROWS_PER_WARP = 8;
static constexpr int MBLOCKS       = BATCH_N / (WARPS_PER_BLK * ROWS_PER_WARP); // 4096

// Replay-safe: g_cnt zeroed by the scan phase after reading; g_base fully
// rewritten each launch; s_recs fully overwritten; g_bar0/g_flag/g_bar2 and
// g_acc/g_done reset by the last main block (main runs after aux in stream
// order, so resets are safe).
__device__ int          g_cnt[NB];
__device__ int          g_base[NB];
__device__ int4         s_recs[BATCH_N];
__device__ unsigned int g_bar0;
__device__ unsigned int g_flag;
__device__ unsigned int g_bar2;
__device__ double       g_acc;
__device__ unsigned int g_done;

// ---- aux: hist + scan + scatter + in-bucket sort, one launch ----------------
__global__ __launch_bounds__(ATHREADS) void glove_aux_kernel(
    const int*   __restrict__ center,
    const int*   __restrict__ outside,
    const float* __restrict__ coocs,
    const float* __restrict__ weighting)
{
    __shared__ int h[NB];        // slice hist (phase 1), cursors (phase 3), cnt (phase 4: [0..127])
    __shared__ int base[NB];     // reserved bases (phase 3), pos (phase 4: [0..127])
    __shared__ int tmp[ATHREADS];

    const int tid  = threadIdx.x;
    const int blk  = blockIdx.x;
    const int lane = tid & 31;
    const int warp = tid >> 5;
    const int idx0 = blk * ACHUNK;

    // ---- phase 1: smem histogram of this block's slice ----
    for (int i = tid; i < NB; i += ATHREADS) h[i] = 0;
    __syncthreads();
    int c[ASPT];
    #pragma unroll
    for (int k = 0; k < ASPT; ++k) {
        c[k] = __ldg(center + idx0 + k * ATHREADS + tid);
        atomicAdd(&h[c[k] >> BUCKET_SHIFT], 1);
    }
    __syncthreads();
    for (int bb = tid; bb < NB; bb += ATHREADS)
        if (h[bb]) atomicAdd(&g_cnt[bb], h[bb]);

    // ---- barrier A, then block 0 scans while others poll the ready flag ----
    __syncthreads();
    if (tid == 0) {
        __threadfence();
        atomicAdd(&g_bar0, 1u);
    }
    if (blk == 0) {
        if (tid == 0)
            while (atomicAdd(&g_bar0, 0u) < (unsigned)ABLOCKS) __nanosleep(64);
        __syncthreads();
        __threadfence();
        // exclusive scan of 1024 counters (2 per thread); re-zero counts
        const int v0 = g_cnt[2 * tid];
        const int v1 = g_cnt[2 * tid + 1];
        g_cnt[2 * tid]     = 0;
        g_cnt[2 * tid + 1] = 0;
        const int sv = v0 + v1;
        tmp[tid] = sv;
        __syncthreads();
        #pragma unroll
        for (int off = 1; off < ATHREADS; off <<= 1) {
            int u = (tid >= off) ? tmp[tid - off] : 0;
            __syncthreads();
            tmp[tid] += u;
            __syncthreads();
        }
        const int pref = tmp[tid] - sv;
        g_base[2 * tid]     = pref;
        g_base[2 * tid + 1] = pref + v0;
        __threadfence();
        __syncthreads();
        if (tid == 0) atomicExch(&g_flag, 1u);
    } else {
        if (tid == 0)
            while (atomicAdd(&g_flag, 0u) == 0u) __nanosleep(64);
        __syncthreads();
        __threadfence();
    }

    // ---- phase 3: scatter (reuse phase-1 hist in h) ----
    for (int bb = tid; bb < NB; bb += ATHREADS) {
        const int n = h[bb];
        base[bb] = n ? atomicAdd(&g_base[bb], n) : 0;
    }
    __syncthreads();
    for (int i = tid; i < NB; i += ATHREADS) h[i] = 0;   // reuse as cursors
    __syncthreads();
    #pragma unroll
    for (int k = 0; k < ASPT; ++k) {
        const int i  = idx0 + k * ATHREADS + tid;
        const int bb = c[k] >> BUCKET_SHIFT;
        const int off = atomicAdd(&h[bb], 1);
        int4 rec;
        rec.x = c[k];
        rec.y = __ldg(outside + i);
        rec.z = __float_as_int(__ldg(coocs + i));
        rec.w = __float_as_int(__ldg(weighting + i));
        s_recs[base[bb] + off] = rec;
    }
    // After all blocks: g_base[b] == END offset of bucket b.

    // ---- barrier B: all scatters visible before any sort ----
    __syncthreads();
    if (tid == 0) {
        __threadfence();
        atomicAdd(&g_bar2, 1u);
        while (atomicAdd(&g_bar2, 0u) < (unsigned)ABLOCKS) __nanosleep(64);
    }
    __syncthreads();
    __threadfence();

    // ---- phase 4: each block counting-sorts buckets blk, blk+128, ... ----
    for (int bb = blk; bb < NB_USED; bb += ABLOCKS) {
        const int s = (bb == 0) ? 0 : g_base[bb - 1];
        const int n = g_base[bb] - s;
        const bool valid = (n > 0 && n <= SORT_CAP);   // uniform across block

        __syncthreads();
        if (tid < 128) h[tid] = 0;                      // cnt
        __syncthreads();

        int4 r0, r1;
        const bool has0 = valid && (tid < n);
        const bool has1 = valid && (tid + ATHREADS < n);
        if (has0) { r0 = s_recs[s + tid];            atomicAdd(&h[r0.x & 127], 1); }
        if (has1) { r1 = s_recs[s + tid + ATHREADS]; atomicAdd(&h[r1.x & 127], 1); }
        __syncthreads();

        if (warp < 4) {                                 // 4-warp shfl scan of 128
            const int idx = warp * 32 + lane;
            const int x   = h[idx];
            int incl = x;
            #pragma unroll
            for (int off = 1; off < 32; off <<= 1) {
                int u = __shfl_up_sync(0xffffffffu, incl, off);
                if (lane >= off) incl += u;
            }
            if (lane == 31) tmp[warp] = incl;           // warp totals
            __syncwarp();
            base[idx] = incl - x;                       // pos (exclusive in warp)
        }
        __syncthreads();
        if (tid < 128) {
            const int w = tid >> 5;
            int add = 0;
            #pragma unroll
            for (int k = 0; k < 3; ++k) if (k < w) add += tmp[k];
            base[tid] += add;
        }
        __syncthreads();

        if (has0) s_recs[s + atomicAdd(&base[r0.x & 127], 1)] = r0;
        if (has1) s_recs[s + atomicAdd(&base[r1.x & 127], 1)] = r1;
    }
}

// ---- main gather with center-row register reuse (R7/R12-proven) -------------
__global__ __launch_bounds__(THREADS, 6) void glove_main_kernel(
    const float* __restrict__ cemb,
    const float* __restrict__ oemb,
    const float* __restrict__ cbias,
    const float* __restrict__ obias,
    float*       __restrict__ out)
{
    const int lane  = threadIdx.x & 31;
    const int warp  = threadIdx.x >> 5;
    const int gwarp = blockIdx.x * WARPS_PER_BLK + warp;

    const float4* __restrict__ cemb4 = reinterpret_cast<const float4*>(cemb);
    const float4* __restrict__ oemb4 = reinterpret_cast<const float4*>(oemb);

    float wsum = 0.0f;
    int   prev = -1;
    float4 a0, a1, a2;
    float  cb = 0.0f;
    a0 = a1 = a2 = make_float4(0.f, 0.f, 0.f, 0.f);

    #pragma unroll 1
    for (int r = 0; r < ROWS_PER_WARP; ++r) {
        const int row = gwarp * ROWS_PER_WARP + r;
        const int4 rec = __ldg(&s_recs[row]);

        const unsigned oo = (unsigned)rec.y * (unsigned)NV4 + (unsigned)lane;
        float4 b0 = __ldg(oemb4 + oo);
        float4 b1 = __ldg(oemb4 + oo + 32);
        float4 b2 = make_float4(0.f, 0.f, 0.f, 0.f);
        if (lane < NV4 - 64) b2 = __ldg(oemb4 + oo + 64);
        const float obv = __ldg(obias + rec.y);

        if (rec.x != prev) {   // warp-uniform branch (records sorted by center)
            const unsigned co = (unsigned)rec.x * (unsigned)NV4 + (unsigned)lane;
            a0 = __ldg(cemb4 + co);
            a1 = __ldg(cemb4 + co + 32);
            a2 = make_float4(0.f, 0.f, 0.f, 0.f);
            if (lane < NV4 - 64) a2 = __ldg(cemb4 + co + 64);
            cb = __ldg(cbias + rec.x);
            prev = rec.x;
        }

        float dot = a0.x * b0.x + a0.y * b0.y + a0.z * b0.z + a0.w * b0.w;
        dot      += a1.x * b1.x + a1.y * b1.y + a1.z * b1.z + a1.w * b1.w;
        dot      += a2.x * b2.x + a2.y * b2.y + a2.z * b2.z + a2.w * b2.w;

        #pragma unroll
        for (int off = 16; off; off >>= 1)
            dot += __shfl_xor_sync(0xffffffffu, dot, off);

        if (lane == 0) {
            const float err = dot + cb + obv - __int_as_float(rec.z);
            wsum += __int_as_float(rec.w) * err * err;
        }
    }

    __shared__ float sh[WARPS_PER_BLK];
    if (lane == 0) sh[warp] = wsum;
    __syncthreads();

    if (threadIdx.x == 0) {
        float s = 0.0f;
        #pragma unroll
        for (int i = 0; i < WARPS_PER_BLK; ++i) s += sh[i];
        atomicAdd(&g_acc, (double)s);

        __threadfence();
        const unsigned t = atomicAdd(&g_done, 1u);
        if (t == (unsigned)(MBLOCKS - 1)) {
            const double v = atomicAdd(&g_acc, 0.0);
            out[0] = (float)v;
            g_acc  = 0.0;
            g_done = 0u;
            g_bar0 = 0u;    // reset aux barriers/flag for next replay
            g_flag = 0u;
            g_bar2 = 0u;
        }
    }
}

extern "C" void kernel_launch(void* const* d_in, const int* in_sizes, int n_in,
                              void* d_out, int out_size) {
    const int*   center    = (const int*)  d_in[0];
    const int*   outside   = (const int*)  d_in[1];
    const float* coocs     = (const float*)d_in[2];
    const float* weighting = (const float*)d_in[3];
    const float* cemb      = (const float*)d_in[4];
    const float* oemb      = (const float*)d_in[5];
    const float* cbias     = (const float*)d_in[6];
    const float* obias     = (const float*)d_in[7];
    float* out = (float*)d_out;

    glove_aux_kernel<<<ABLOCKS, ATHREADS>>>(center, outside, coocs, weighting);
    glove_main_kernel<<<MBLOCKS, THREADS>>>(cemb, oemb, cbias, obias, out);
}